// round 13
// baseline (speedup 1.0000x reference)
#include <cuda_runtime.h>

// LSTM: B=1024, T=2048, H=32, I=1.
// One warp per batch element; lane j owns hidden unit j.
// fp16-pipe GEMV, GATE-MAJOR schedule: per gate 16 HFMA2 (2 chains x depth 8)
// immediately followed by that gate's merge + MUFU.TANH, so each gate's tail
// hides under the next gate's HFMA2 stream. Order: f, i, g (c-fma early), o.
// h broadcast as fp16[32] in smem (4x LDS.128). c/x/bias/activations fp32.
// sigmoid(a)=0.5*tanh(a/2)+0.5 with pre-scaled weights.

#define B_ 1024
#define T_ 2048
#define H_ 32

typedef unsigned int u32;
typedef unsigned long long u64;

static __device__ __forceinline__ u32 hfma2(u32 a, u32 b, u32 c) {
    u32 d;
    asm("fma.rn.f16x2 %0, %1, %2, %3;" : "=r"(d) : "r"(a), "r"(b), "r"(c));
    return d;
}
static __device__ __forceinline__ u32 hadd2(u32 a, u32 b) {
    u32 d;
    asm("add.rn.f16x2 %0, %1, %2;" : "=r"(d) : "r"(a), "r"(b));
    return d;
}
static __device__ __forceinline__ u32 prmt_swap(u32 a) {
    u32 d;
    asm("prmt.b32 %0, %1, 0, 0x1032;" : "=r"(d) : "r"(a));
    return d;
}
static __device__ __forceinline__ u32 pkh2(float lo, float hi) {
    u32 d;
    asm("cvt.rn.f16x2.f32 %0, %1, %2;" : "=r"(d) : "f"(hi), "f"(lo));
    return d;
}
static __device__ __forceinline__ float f16lo(u32 v) {
    unsigned short lo, hi;
    float f;
    asm("mov.b32 {%0, %1}, %2;" : "=h"(lo), "=h"(hi) : "r"(v));
    asm("cvt.f32.f16 %0, %1;" : "=f"(f) : "h"(lo));
    return f;
}
static __device__ __forceinline__ unsigned short f32_to_h(float f) {
    unsigned short h;
    asm("cvt.rn.f16.f32 %0, %1;" : "=h"(h) : "f"(f));
    return h;
}
static __device__ __forceinline__ float tanhf_(float x) {
    float r; asm("tanh.approx.f32 %0, %1;" : "=f"(r) : "f"(x)); return r;
}
static __device__ __forceinline__ void lds128(u32& r0, u32& r1, u32& r2, u32& r3,
                                              unsigned addr) {
    asm volatile("ld.shared.v4.b32 {%0, %1, %2, %3}, [%4];"
                 : "=r"(r0), "=r"(r1), "=r"(r2), "=r"(r3) : "r"(addr));
}
static __device__ __forceinline__ void sts16(unsigned addr, unsigned short v) {
    asm volatile("st.shared.b16 [%0], %1;" :: "r"(addr), "h"(v));
}
static __device__ __forceinline__ u64 pk2f(float lo, float hi) {
    u64 r;
    asm("mov.b64 %0, {%1, %2};" : "=l"(r) : "f"(lo), "f"(hi));
    return r;
}
static __device__ __forceinline__ void upk2f(u64 v, float& lo, float& hi) {
    asm("mov.b64 {%0, %1}, %2;" : "=f"(lo), "=f"(hi) : "l"(v));
}
static __device__ __forceinline__ u64 fma2f(u64 a, u64 b, u64 c) {
    u64 d;
    asm("fma.rn.f32x2 %0, %1, %2, %3;" : "=l"(d) : "l"(a), "l"(b), "l"(c));
    return d;
}

// One gate: 2 HFMA2 chains (depth 8) over hp[0..15], merge to scalar fp32 + xb.
#define GATE_DOT(W, XB, OUT)                                         \
    do {                                                             \
        u32 c0 = 0u, c1 = 0u;                                        \
        _Pragma("unroll")                                            \
        for (int m = 0; m < 16; m += 2) {                            \
            c0 = hfma2(hp[m],     (W)[m],     c0);                   \
            c1 = hfma2(hp[m + 1], (W)[m + 1], c1);                   \
        }                                                            \
        u32 s = hadd2(c0, c1);                                       \
        s = hadd2(s, prmt_swap(s));                                  \
        (OUT) = f16lo(s) + (XB);                                     \
    } while (0)

__global__ void __launch_bounds__(32)
lstm_kernel(const float* __restrict__ x,
            const float* __restrict__ W_ih,
            const float* __restrict__ W_hh,
            const float* __restrict__ b_ih,
            const float* __restrict__ b_hh,
            const float* __restrict__ W_out,
            const float* __restrict__ b_out,
            float* __restrict__ out) {
    const int j = threadIdx.x;   // hidden unit
    const int b = blockIdx.x;    // batch element

    __shared__ __align__(16) unsigned short hb16[2][H_];  // fp16 h, double-buffered
    __shared__ float pbuf[32][33];                        // output partials
    volatile float (*pv)[33] = (volatile float (*)[33])pbuf;

    const float sI = 0.5f, sF = 0.5f, sG = 1.0f, sO = 0.5f;

    // fp16x2 k-pair packed recurrent weights, per gate.
    u32 wi[16], wf[16], wg[16], wo[16];
#pragma unroll
    for (int m = 0; m < 16; m++) {
        const int k = 2 * m;
        wi[m] = pkh2(sI * W_hh[(0 * H_ + j) * H_ + k], sI * W_hh[(0 * H_ + j) * H_ + k + 1]);
        wf[m] = pkh2(sF * W_hh[(1 * H_ + j) * H_ + k], sF * W_hh[(1 * H_ + j) * H_ + k + 1]);
        wg[m] = pkh2(sG * W_hh[(2 * H_ + j) * H_ + k], sG * W_hh[(2 * H_ + j) * H_ + k + 1]);
        wo[m] = pkh2(sO * W_hh[(3 * H_ + j) * H_ + k], sO * W_hh[(3 * H_ + j) * H_ + k + 1]);
    }
    // fp32 input weights / biases, packed (i,f) and (g,o) for FFMA2.
    const u64 wih_if = pk2f(sI * W_ih[0 * H_ + j], sF * W_ih[1 * H_ + j]);
    const u64 wih_go = pk2f(sG * W_ih[2 * H_ + j], sO * W_ih[3 * H_ + j]);
    const u64 bs_if  = pk2f(sI * (b_ih[0 * H_ + j] + b_hh[0 * H_ + j]),
                            sF * (b_ih[1 * H_ + j] + b_hh[1 * H_ + j]));
    const u64 bs_go  = pk2f(sG * (b_ih[2 * H_ + j] + b_hh[2 * H_ + j]),
                            sO * (b_ih[3 * H_ + j] + b_hh[3 * H_ + j]));
    const float wout = W_out[j];
    const float bout = b_out[0];

    const unsigned hb0 = (unsigned)__cvta_generic_to_shared(&hb16[0][0]);
    const unsigned hb1 = hb0 + (unsigned)(H_ * sizeof(unsigned short));

    float c = 0.0f;
    sts16(hb0 + j * 2, (unsigned short)0);   // h_{-1} = 0

    const float* xb = x + (size_t)b * T_;
    float* ob = out + (size_t)b * T_;
    float xc = xb[0];

    for (int t0 = 0; t0 < T_; t0 += 32) {
#pragma unroll 4
        for (int tt = 0; tt < 32; ++tt) {
            const int t = t0 + tt;
            const int tn = (t + 1 < T_) ? (t + 1) : (T_ - 1);
            const float xn = xb[tn];   // prefetch next x

            const unsigned rd = (t & 1) ? hb1 : hb0;
            const unsigned wr = (((t & 1) ? hb0 : hb1)) + j * 2;

            // Load full fp16 h vector: 4x LDS.128 broadcast.
            u32 hp[16];
            lds128(hp[0],  hp[1],  hp[2],  hp[3],  rd);
            lds128(hp[4],  hp[5],  hp[6],  hp[7],  rd + 16);
            lds128(hp[8],  hp[9],  hp[10], hp[11], rd + 32);
            lds128(hp[12], hp[13], hp[14], hp[15], rd + 48);

            // fp32 x+bias terms via 2x FFMA2 (overlaps LDS latency).
            const u64 xd = pk2f(xc, xc);
            float xbi, xbf, xbg, xbo;
            upk2f(fma2f(xd, wih_if, bs_if), xbi, xbf);
            upk2f(fma2f(xd, wih_go, bs_go), xbg, xbo);

            // Gate-major: each gate's merge+tanh hides under the next gate's
            // HFMA2 stream. Order f, i, g (c-path early), o.
            float pf, pi, pg, po;
            GATE_DOT(wf, xbf, pf);
            const float tf = tanhf_(pf);
            GATE_DOT(wi, xbi, pi);
            const float ti = tanhf_(pi);
            GATE_DOT(wg, xbg, pg);
            const float g_ = tanhf_(pg);
            GATE_DOT(wo, xbo, po);
            const float to = tanhf_(po);

            const float f_ = fmaf(tf, 0.5f, 0.5f);
            const float i_ = fmaf(ti, 0.5f, 0.5f);
            c = fmaf(f_, c, i_ * g_);
            const float tc = tanhf_(c);
            const float o_ = fmaf(to, 0.5f, 0.5f);
            const float h = o_ * tc;

            sts16(wr, f32_to_h(h));        // fp16 h broadcast (converged warp)
            pv[tt][j] = h * wout;
            xc = xn;
        }
        // Transposed reduction: lane j sums the 32 partials of timestep t0+j.
        float s0 = 0.0f, s1 = 0.0f, s2 = 0.0f, s3 = 0.0f;
#pragma unroll
        for (int k = 0; k < 32; k += 4) {
            s0 += pv[j][k];
            s1 += pv[j][k + 1];
            s2 += pv[j][k + 2];
            s3 += pv[j][k + 3];
        }
        ob[t0 + j] = (s0 + s1) + (s2 + s3) + bout;
    }
}

extern "C" void kernel_launch(void* const* d_in, const int* in_sizes, int n_in,
                              void* d_out, int out_size) {
    const float* x     = (const float*)d_in[0];
    const float* W_ih  = (const float*)d_in[1];
    const float* W_hh  = (const float*)d_in[2];
    const float* b_ih  = (const float*)d_in[3];
    const float* b_hh  = (const float*)d_in[4];
    const float* W_out = (const float*)d_in[5];
    const float* b_out = (const float*)d_in[6];
    float* out = (float*)d_out;

    lstm_kernel<<<B_, 32>>>(x, W_ih, W_hh, b_ih, b_hh, W_out, b_out, out);
}

// round 14
// speedup vs baseline: 1.0032x; 1.0032x over previous
#include <cuda_runtime.h>

// LSTM: B=1024, T=2048, H=32, I=1.
// One warp per batch element; lane j owns hidden unit j.
// fp16-pipe GEMV, GATE-MAJOR schedule: per gate 16 HFMA2 (2 chains x depth 8)
// immediately followed by that gate's merge + MUFU.TANH, so each gate's tail
// hides under the next gate's HFMA2 stream. Order: f, i, g (c-fma early), o.
// h broadcast as fp16[32] in smem (4x LDS.128). c/x/bias/activations fp32.
// sigmoid(a)=0.5*tanh(a/2)+0.5 with pre-scaled weights.

#define B_ 1024
#define T_ 2048
#define H_ 32

typedef unsigned int u32;
typedef unsigned long long u64;

static __device__ __forceinline__ u32 hfma2(u32 a, u32 b, u32 c) {
    u32 d;
    asm("fma.rn.f16x2 %0, %1, %2, %3;" : "=r"(d) : "r"(a), "r"(b), "r"(c));
    return d;
}
static __device__ __forceinline__ u32 hadd2(u32 a, u32 b) {
    u32 d;
    asm("add.rn.f16x2 %0, %1, %2;" : "=r"(d) : "r"(a), "r"(b));
    return d;
}
static __device__ __forceinline__ u32 prmt_swap(u32 a) {
    u32 d;
    asm("prmt.b32 %0, %1, 0, 0x1032;" : "=r"(d) : "r"(a));
    return d;
}
static __device__ __forceinline__ u32 pkh2(float lo, float hi) {
    u32 d;
    asm("cvt.rn.f16x2.f32 %0, %1, %2;" : "=r"(d) : "f"(hi), "f"(lo));
    return d;
}
static __device__ __forceinline__ float f16lo(u32 v) {
    unsigned short lo, hi;
    float f;
    asm("mov.b32 {%0, %1}, %2;" : "=h"(lo), "=h"(hi) : "r"(v));
    asm("cvt.f32.f16 %0, %1;" : "=f"(f) : "h"(lo));
    return f;
}
static __device__ __forceinline__ unsigned short f32_to_h(float f) {
    unsigned short h;
    asm("cvt.rn.f16.f32 %0, %1;" : "=h"(h) : "f"(f));
    return h;
}
static __device__ __forceinline__ float tanhf_(float x) {
    float r; asm("tanh.approx.f32 %0, %1;" : "=f"(r) : "f"(x)); return r;
}
static __device__ __forceinline__ void lds128(u32& r0, u32& r1, u32& r2, u32& r3,
                                              unsigned addr) {
    asm volatile("ld.shared.v4.b32 {%0, %1, %2, %3}, [%4];"
                 : "=r"(r0), "=r"(r1), "=r"(r2), "=r"(r3) : "r"(addr));
}
static __device__ __forceinline__ void sts16(unsigned addr, unsigned short v) {
    asm volatile("st.shared.b16 [%0], %1;" :: "r"(addr), "h"(v));
}
static __device__ __forceinline__ u64 pk2f(float lo, float hi) {
    u64 r;
    asm("mov.b64 %0, {%1, %2};" : "=l"(r) : "f"(lo), "f"(hi));
    return r;
}
static __device__ __forceinline__ void upk2f(u64 v, float& lo, float& hi) {
    asm("mov.b64 {%0, %1}, %2;" : "=f"(lo), "=f"(hi) : "l"(v));
}
static __device__ __forceinline__ u64 fma2f(u64 a, u64 b, u64 c) {
    u64 d;
    asm("fma.rn.f32x2 %0, %1, %2, %3;" : "=l"(d) : "l"(a), "l"(b), "l"(c));
    return d;
}

// One gate: 2 HFMA2 chains (depth 8) over hp[0..15], merge to scalar fp32 + xb.
#define GATE_DOT(W, XB, OUT)                                         \
    do {                                                             \
        u32 c0 = 0u, c1 = 0u;                                        \
        _Pragma("unroll")                                            \
        for (int m = 0; m < 16; m += 2) {                            \
            c0 = hfma2(hp[m],     (W)[m],     c0);                   \
            c1 = hfma2(hp[m + 1], (W)[m + 1], c1);                   \
        }                                                            \
        u32 s = hadd2(c0, c1);                                       \
        s = hadd2(s, prmt_swap(s));                                  \
        (OUT) = f16lo(s) + (XB);                                     \
    } while (0)

__global__ void __launch_bounds__(32)
lstm_kernel(const float* __restrict__ x,
            const float* __restrict__ W_ih,
            const float* __restrict__ W_hh,
            const float* __restrict__ b_ih,
            const float* __restrict__ b_hh,
            const float* __restrict__ W_out,
            const float* __restrict__ b_out,
            float* __restrict__ out) {
    const int j = threadIdx.x;   // hidden unit
    const int b = blockIdx.x;    // batch element

    __shared__ __align__(16) unsigned short hb16[2][H_];  // fp16 h, double-buffered
    __shared__ float pbuf[32][33];                        // output partials
    volatile float (*pv)[33] = (volatile float (*)[33])pbuf;

    const float sI = 0.5f, sF = 0.5f, sG = 1.0f, sO = 0.5f;

    // fp16x2 k-pair packed recurrent weights, per gate.
    u32 wi[16], wf[16], wg[16], wo[16];
#pragma unroll
    for (int m = 0; m < 16; m++) {
        const int k = 2 * m;
        wi[m] = pkh2(sI * W_hh[(0 * H_ + j) * H_ + k], sI * W_hh[(0 * H_ + j) * H_ + k + 1]);
        wf[m] = pkh2(sF * W_hh[(1 * H_ + j) * H_ + k], sF * W_hh[(1 * H_ + j) * H_ + k + 1]);
        wg[m] = pkh2(sG * W_hh[(2 * H_ + j) * H_ + k], sG * W_hh[(2 * H_ + j) * H_ + k + 1]);
        wo[m] = pkh2(sO * W_hh[(3 * H_ + j) * H_ + k], sO * W_hh[(3 * H_ + j) * H_ + k + 1]);
    }
    // fp32 input weights / biases, packed (i,f) and (g,o) for FFMA2.
    const u64 wih_if = pk2f(sI * W_ih[0 * H_ + j], sF * W_ih[1 * H_ + j]);
    const u64 wih_go = pk2f(sG * W_ih[2 * H_ + j], sO * W_ih[3 * H_ + j]);
    const u64 bs_if  = pk2f(sI * (b_ih[0 * H_ + j] + b_hh[0 * H_ + j]),
                            sF * (b_ih[1 * H_ + j] + b_hh[1 * H_ + j]));
    const u64 bs_go  = pk2f(sG * (b_ih[2 * H_ + j] + b_hh[2 * H_ + j]),
                            sO * (b_ih[3 * H_ + j] + b_hh[3 * H_ + j]));
    const float wout = W_out[j];
    const float bout = b_out[0];

    const unsigned hb0 = (unsigned)__cvta_generic_to_shared(&hb16[0][0]);
    const unsigned hb1 = hb0 + (unsigned)(H_ * sizeof(unsigned short));

    float c = 0.0f;
    sts16(hb0 + j * 2, (unsigned short)0);   // h_{-1} = 0

    const float* xb = x + (size_t)b * T_;
    float* ob = out + (size_t)b * T_;
    float xc = xb[0];

    for (int t0 = 0; t0 < T_; t0 += 32) {
#pragma unroll 4
        for (int tt = 0; tt < 32; ++tt) {
            const int t = t0 + tt;
            const int tn = (t + 1 < T_) ? (t + 1) : (T_ - 1);
            const float xn = xb[tn];   // prefetch next x

            const unsigned rd = (t & 1) ? hb1 : hb0;
            const unsigned wr = (((t & 1) ? hb0 : hb1)) + j * 2;

            // Load full fp16 h vector: 4x LDS.128 broadcast.
            u32 hp[16];
            lds128(hp[0],  hp[1],  hp[2],  hp[3],  rd);
            lds128(hp[4],  hp[5],  hp[6],  hp[7],  rd + 16);
            lds128(hp[8],  hp[9],  hp[10], hp[11], rd + 32);
            lds128(hp[12], hp[13], hp[14], hp[15], rd + 48);

            // fp32 x+bias terms via 2x FFMA2 (overlaps LDS latency).
            const u64 xd = pk2f(xc, xc);
            float xbi, xbf, xbg, xbo;
            upk2f(fma2f(xd, wih_if, bs_if), xbi, xbf);
            upk2f(fma2f(xd, wih_go, bs_go), xbg, xbo);

            // Gate-major: each gate's merge+tanh hides under the next gate's
            // HFMA2 stream. Order f, i, g (c-path early), o.
            float pf, pi, pg, po;
            GATE_DOT(wf, xbf, pf);
            const float tf = tanhf_(pf);
            GATE_DOT(wi, xbi, pi);
            const float ti = tanhf_(pi);
            GATE_DOT(wg, xbg, pg);
            const float g_ = tanhf_(pg);
            GATE_DOT(wo, xbo, po);
            const float to = tanhf_(po);

            const float f_ = fmaf(tf, 0.5f, 0.5f);
            const float i_ = fmaf(ti, 0.5f, 0.5f);
            c = fmaf(f_, c, i_ * g_);
            const float tc = tanhf_(c);
            const float o_ = fmaf(to, 0.5f, 0.5f);
            const float h = o_ * tc;

            sts16(wr, f32_to_h(h));        // fp16 h broadcast (converged warp)
            pv[tt][j] = h * wout;
            xc = xn;
        }
        // Transposed reduction: lane j sums the 32 partials of timestep t0+j.
        float s0 = 0.0f, s1 = 0.0f, s2 = 0.0f, s3 = 0.0f;
#pragma unroll
        for (int k = 0; k < 32; k += 4) {
            s0 += pv[j][k];
            s1 += pv[j][k + 1];
            s2 += pv[j][k + 2];
            s3 += pv[j][k + 3];
        }
        ob[t0 + j] = (s0 + s1) + (s2 + s3) + bout;
    }
}

extern "C" void kernel_launch(void* const* d_in, const int* in_sizes, int n_in,
                              void* d_out, int out_size) {
    const float* x     = (const float*)d_in[0];
    const float* W_ih  = (const float*)d_in[1];
    const float* W_hh  = (const float*)d_in[2];
    const float* b_ih  = (const float*)d_in[3];
    const float* b_hh  = (const float*)d_in[4];
    const float* W_out = (const float*)d_in[5];
    const float* b_out = (const float*)d_in[6];
    float* out = (float*)d_out;

    lstm_kernel<<<B_, 32>>>(x, W_ih, W_hh, b_ih, b_hh, W_out, b_out, out);
}

// round 15
// speedup vs baseline: 1.0039x; 1.0006x over previous
#include <cuda_runtime.h>

// LSTM: B=1024, T=2048, H=32, I=1.
// One warp per batch element; lane j owns hidden unit j.
// fp16-pipe GEMV, GATE-MAJOR schedule: per gate 16 HFMA2 (2 chains x depth 8)
// immediately followed by that gate's merge + MUFU.TANH, so each gate's tail
// hides under the next gate's HFMA2 stream. Order: f, i, g (c-fma early), o.
// h broadcast as fp16[32] in smem (4x LDS.128). c/x/bias/activations fp32.
// sigmoid(a)=0.5*tanh(a/2)+0.5 with pre-scaled weights.

#define B_ 1024
#define T_ 2048
#define H_ 32

typedef unsigned int u32;
typedef unsigned long long u64;

static __device__ __forceinline__ u32 hfma2(u32 a, u32 b, u32 c) {
    u32 d;
    asm("fma.rn.f16x2 %0, %1, %2, %3;" : "=r"(d) : "r"(a), "r"(b), "r"(c));
    return d;
}
static __device__ __forceinline__ u32 hadd2(u32 a, u32 b) {
    u32 d;
    asm("add.rn.f16x2 %0, %1, %2;" : "=r"(d) : "r"(a), "r"(b));
    return d;
}
static __device__ __forceinline__ u32 prmt_swap(u32 a) {
    u32 d;
    asm("prmt.b32 %0, %1, 0, 0x1032;" : "=r"(d) : "r"(a));
    return d;
}
static __device__ __forceinline__ u32 pkh2(float lo, float hi) {
    u32 d;
    asm("cvt.rn.f16x2.f32 %0, %1, %2;" : "=r"(d) : "f"(hi), "f"(lo));
    return d;
}
static __device__ __forceinline__ float f16lo(u32 v) {
    unsigned short lo, hi;
    float f;
    asm("mov.b32 {%0, %1}, %2;" : "=h"(lo), "=h"(hi) : "r"(v));
    asm("cvt.f32.f16 %0, %1;" : "=f"(f) : "h"(lo));
    return f;
}
static __device__ __forceinline__ unsigned short f32_to_h(float f) {
    unsigned short h;
    asm("cvt.rn.f16.f32 %0, %1;" : "=h"(h) : "f"(f));
    return h;
}
static __device__ __forceinline__ float tanhf_(float x) {
    float r; asm("tanh.approx.f32 %0, %1;" : "=f"(r) : "f"(x)); return r;
}
static __device__ __forceinline__ void lds128(u32& r0, u32& r1, u32& r2, u32& r3,
                                              unsigned addr) {
    asm volatile("ld.shared.v4.b32 {%0, %1, %2, %3}, [%4];"
                 : "=r"(r0), "=r"(r1), "=r"(r2), "=r"(r3) : "r"(addr));
}
static __device__ __forceinline__ void sts16(unsigned addr, unsigned short v) {
    asm volatile("st.shared.b16 [%0], %1;" :: "r"(addr), "h"(v));
}
static __device__ __forceinline__ u64 pk2f(float lo, float hi) {
    u64 r;
    asm("mov.b64 %0, {%1, %2};" : "=l"(r) : "f"(lo), "f"(hi));
    return r;
}
static __device__ __forceinline__ void upk2f(u64 v, float& lo, float& hi) {
    asm("mov.b64 {%0, %1}, %2;" : "=f"(lo), "=f"(hi) : "l"(v));
}
static __device__ __forceinline__ u64 fma2f(u64 a, u64 b, u64 c) {
    u64 d;
    asm("fma.rn.f32x2 %0, %1, %2, %3;" : "=l"(d) : "l"(a), "l"(b), "l"(c));
    return d;
}

// One gate: 2 HFMA2 chains (depth 8) over hp[0..15], merge to scalar fp32 + xb.
#define GATE_DOT(W, XB, OUT)                                         \
    do {                                                             \
        u32 c0 = 0u, c1 = 0u;                                        \
        _Pragma("unroll")                                            \
        for (int m = 0; m < 16; m += 2) {                            \
            c0 = hfma2(hp[m],     (W)[m],     c0);                   \
            c1 = hfma2(hp[m + 1], (W)[m + 1], c1);                   \
        }                                                            \
        u32 s = hadd2(c0, c1);                                       \
        s = hadd2(s, prmt_swap(s));                                  \
        (OUT) = f16lo(s) + (XB);                                     \
    } while (0)

__global__ void __launch_bounds__(32)
lstm_kernel(const float* __restrict__ x,
            const float* __restrict__ W_ih,
            const float* __restrict__ W_hh,
            const float* __restrict__ b_ih,
            const float* __restrict__ b_hh,
            const float* __restrict__ W_out,
            const float* __restrict__ b_out,
            float* __restrict__ out) {
    const int j = threadIdx.x;   // hidden unit
    const int b = blockIdx.x;    // batch element

    __shared__ __align__(16) unsigned short hb16[2][H_];  // fp16 h, double-buffered
    __shared__ float pbuf[32][33];                        // output partials
    volatile float (*pv)[33] = (volatile float (*)[33])pbuf;

    const float sI = 0.5f, sF = 0.5f, sG = 1.0f, sO = 0.5f;

    // fp16x2 k-pair packed recurrent weights, per gate.
    u32 wi[16], wf[16], wg[16], wo[16];
#pragma unroll
    for (int m = 0; m < 16; m++) {
        const int k = 2 * m;
        wi[m] = pkh2(sI * W_hh[(0 * H_ + j) * H_ + k], sI * W_hh[(0 * H_ + j) * H_ + k + 1]);
        wf[m] = pkh2(sF * W_hh[(1 * H_ + j) * H_ + k], sF * W_hh[(1 * H_ + j) * H_ + k + 1]);
        wg[m] = pkh2(sG * W_hh[(2 * H_ + j) * H_ + k], sG * W_hh[(2 * H_ + j) * H_ + k + 1]);
        wo[m] = pkh2(sO * W_hh[(3 * H_ + j) * H_ + k], sO * W_hh[(3 * H_ + j) * H_ + k + 1]);
    }
    // fp32 input weights / biases, packed (i,f) and (g,o) for FFMA2.
    const u64 wih_if = pk2f(sI * W_ih[0 * H_ + j], sF * W_ih[1 * H_ + j]);
    const u64 wih_go = pk2f(sG * W_ih[2 * H_ + j], sO * W_ih[3 * H_ + j]);
    const u64 bs_if  = pk2f(sI * (b_ih[0 * H_ + j] + b_hh[0 * H_ + j]),
                            sF * (b_ih[1 * H_ + j] + b_hh[1 * H_ + j]));
    const u64 bs_go  = pk2f(sG * (b_ih[2 * H_ + j] + b_hh[2 * H_ + j]),
                            sO * (b_ih[3 * H_ + j] + b_hh[3 * H_ + j]));
    const float wout = W_out[j];
    const float bout = b_out[0];

    const unsigned hb0 = (unsigned)__cvta_generic_to_shared(&hb16[0][0]);
    const unsigned hb1 = hb0 + (unsigned)(H_ * sizeof(unsigned short));

    float c = 0.0f;
    sts16(hb0 + j * 2, (unsigned short)0);   // h_{-1} = 0

    const float* xb = x + (size_t)b * T_;
    float* ob = out + (size_t)b * T_;
    float xc = xb[0];

    for (int t0 = 0; t0 < T_; t0 += 32) {
#pragma unroll 4
        for (int tt = 0; tt < 32; ++tt) {
            const int t = t0 + tt;
            const int tn = (t + 1 < T_) ? (t + 1) : (T_ - 1);
            const float xn = xb[tn];   // prefetch next x

            const unsigned rd = (t & 1) ? hb1 : hb0;
            const unsigned wr = (((t & 1) ? hb0 : hb1)) + j * 2;

            // Load full fp16 h vector: 4x LDS.128 broadcast.
            u32 hp[16];
            lds128(hp[0],  hp[1],  hp[2],  hp[3],  rd);
            lds128(hp[4],  hp[5],  hp[6],  hp[7],  rd + 16);
            lds128(hp[8],  hp[9],  hp[10], hp[11], rd + 32);
            lds128(hp[12], hp[13], hp[14], hp[15], rd + 48);

            // fp32 x+bias terms via 2x FFMA2 (overlaps LDS latency).
            const u64 xd = pk2f(xc, xc);
            float xbi, xbf, xbg, xbo;
            upk2f(fma2f(xd, wih_if, bs_if), xbi, xbf);
            upk2f(fma2f(xd, wih_go, bs_go), xbg, xbo);

            // Gate-major: each gate's merge+tanh hides under the next gate's
            // HFMA2 stream. Order f, i, g (c-path early), o.
            float pf, pi, pg, po;
            GATE_DOT(wf, xbf, pf);
            const float tf = tanhf_(pf);
            GATE_DOT(wi, xbi, pi);
            const float ti = tanhf_(pi);
            GATE_DOT(wg, xbg, pg);
            const float g_ = tanhf_(pg);
            GATE_DOT(wo, xbo, po);
            const float to = tanhf_(po);

            const float f_ = fmaf(tf, 0.5f, 0.5f);
            const float i_ = fmaf(ti, 0.5f, 0.5f);
            c = fmaf(f_, c, i_ * g_);
            const float tc = tanhf_(c);
            const float o_ = fmaf(to, 0.5f, 0.5f);
            const float h = o_ * tc;

            sts16(wr, f32_to_h(h));        // fp16 h broadcast (converged warp)
            pv[tt][j] = h * wout;
            xc = xn;
        }
        // Transposed reduction: lane j sums the 32 partials of timestep t0+j.
        float s0 = 0.0f, s1 = 0.0f, s2 = 0.0f, s3 = 0.0f;
#pragma unroll
        for (int k = 0; k < 32; k += 4) {
            s0 += pv[j][k];
            s1 += pv[j][k + 1];
            s2 += pv[j][k + 2];
            s3 += pv[j][k + 3];
        }
        ob[t0 + j] = (s0 + s1) + (s2 + s3) + bout;
    }
}

extern "C" void kernel_launch(void* const* d_in, const int* in_sizes, int n_in,
                              void* d_out, int out_size) {
    const float* x     = (const float*)d_in[0];
    const float* W_ih  = (const float*)d_in[1];
    const float* W_hh  = (const float*)d_in[2];
    const float* b_ih  = (const float*)d_in[3];
    const float* b_hh  = (const float*)d_in[4];
    const float* W_out = (const float*)d_in[5];
    const float* b_out = (const float*)d_in[6];
    float* out = (float*)d_out;

    lstm_kernel<<<B_, 32>>>(x, W_ih, W_hh, b_ih, b_hh, W_out, b_out, out);
}